// round 6
// baseline (speedup 1.0000x reference)
#include <cuda_runtime.h>
#include <cuda_bf16.h>
#include <cstdint>
#include <cmath>

#define BATCH 8
#define CH    512
#define NTOK  4096

// ---------------- scratch (device globals) ----------------
__device__ __nv_bfloat16 g_Wt[4 * CH * CH];           // transposed bf16 weights [c][d]
__device__ __nv_bfloat16 g_X [3 * BATCH * CH * NTOK]; // bf16 q,k,v in [b][c][n]
__device__ __nv_bfloat16 g_Q [BATCH * CH * NTOK];
__device__ __nv_bfloat16 g_K [BATCH * CH * NTOK];
__device__ __nv_bfloat16 g_V [BATCH * CH * NTOK];
__device__ __nv_bfloat16 g_M [BATCH * CH * NTOK];
__device__ float g_Ksum[BATCH * CH];

// ---------------- helpers ----------------
__device__ __forceinline__ uint32_t smem_u32(const void* p) {
    uint32_t a;
    asm("{ .reg .u64 t; cvta.to.shared.u64 t, %1; cvt.u32.u64 %0, t; }" : "=r"(a) : "l"(p));
    return a;
}
__device__ __forceinline__ uint32_t bf2u(__nv_bfloat162 h) {
    union { __nv_bfloat162 h; uint32_t u; } z; z.h = h; return z.u;
}
__device__ __forceinline__ void mma_bf16(float c[4], const uint32_t a[4], const uint32_t b[2]) {
    asm volatile(
        "mma.sync.aligned.m16n8k16.row.col.f32.bf16.bf16.f32 "
        "{%0,%1,%2,%3}, {%4,%5,%6,%7}, {%8,%9}, {%0,%1,%2,%3};"
        : "+f"(c[0]), "+f"(c[1]), "+f"(c[2]), "+f"(c[3])
        : "r"(a[0]), "r"(a[1]), "r"(a[2]), "r"(a[3]), "r"(b[0]), "r"(b[1]));
}
__device__ __forceinline__ void ldsm_x4_t(uint32_t r[4], uint32_t addr) {
    asm volatile("ldmatrix.sync.aligned.m8n8.x4.trans.shared.b16 {%0,%1,%2,%3}, [%4];"
                 : "=r"(r[0]), "=r"(r[1]), "=r"(r[2]), "=r"(r[3]) : "r"(addr));
}
#define CP16(dst, src) \
    asm volatile("cp.async.cg.shared.global [%0], [%1], 16;" :: "r"(dst), "l"(src) : "memory")
#define CP_COMMIT() asm volatile("cp.async.commit_group;" ::: "memory")
#define CP_WAIT(n)  asm volatile("cp.async.wait_group %0;" :: "n"(n) : "memory")

// =====================================================================
// weight prep: W fp32 [d][c] -> bf16 [c][d]  (grid 16,16,4); also zeros g_Ksum
// =====================================================================
__global__ __launch_bounds__(256) void wprep(
    const float* __restrict__ W0, const float* __restrict__ W1,
    const float* __restrict__ W2, const float* __restrict__ W3,
    __nv_bfloat16* __restrict__ D)
{
    __shared__ float t[32][33];
    if (blockIdx.z == 0 && blockIdx.y == 0)
        g_Ksum[blockIdx.x * 256 + threadIdx.x] = 0.f;
    const int z = blockIdx.z;
    const float* S = (z == 0) ? W0 : (z == 1) ? W1 : (z == 2) ? W2 : W3;
    __nv_bfloat16* Dz = D + (size_t)z * CH * CH;
    const int d0 = blockIdx.x * 32, c0 = blockIdx.y * 32;
    const int x = threadIdx.x & 31, y = threadIdx.x >> 5;
#pragma unroll
    for (int i = 0; i < 4; i++)
        t[y + 8 * i][x] = S[(size_t)(d0 + y + 8 * i) * CH + c0 + x];
    __syncthreads();
    const int m2 = threadIdx.x & 15, r0 = threadIdx.x >> 4;
#pragma unroll
    for (int i = 0; i < 2; i++) {
        const int r = r0 + 16 * i;
        __nv_bfloat162 h = __float22bfloat162_rn(make_float2(t[m2 * 2][r], t[m2 * 2 + 1][r]));
        *(__nv_bfloat162*)&Dz[(size_t)(c0 + r) * CH + d0 + m2 * 2] = h;
    }
}

// =====================================================================
// input prep: fp32 -> bf16 elementwise (grid 8192,1,3)
// =====================================================================
__global__ __launch_bounds__(256) void xconv(
    const float4* __restrict__ s0, const float4* __restrict__ s1,
    const float4* __restrict__ s2, uint4* __restrict__ d)
{
    const int z = blockIdx.z;
    const float4* s = (z == 0) ? s0 : (z == 1) ? s1 : s2;
    uint4* dz = d + (size_t)z * (BATCH * CH * NTOK / 8);
    const size_t i = (size_t)blockIdx.x * 256 + threadIdx.x;
    float4 a = s[2 * i], b = s[2 * i + 1];
    uint4 o;
    o.x = bf2u(__float22bfloat162_rn(make_float2(a.x, a.y)));
    o.y = bf2u(__float22bfloat162_rn(make_float2(a.z, a.w)));
    o.z = bf2u(__float22bfloat162_rn(make_float2(b.x, b.y)));
    o.w = bf2u(__float22bfloat162_rn(make_float2(b.z, b.w)));
    dz[i] = o;
}

// =====================================================================
// GEMM: C[b,d,n] = sum_c At[c,d] * B[b,c,n]  (+elu+1 | +bias | +ksum atomics)
// BM=BN=128, BK=32, 4-stage cp.async, 256 thr, 8 warps (4m x 2n), 32x64.
// =====================================================================
#define STG_SZ 16384
#define GEMM_SMEM (4 * STG_SZ)

template<bool PROJ, typename OutT, bool BIAS>
__global__ __launch_bounds__(256, 2) void gemm_ca(
    const __nv_bfloat16* __restrict__ A0, const __nv_bfloat16* __restrict__ A1,
    const __nv_bfloat16* __restrict__ A2,
    const __nv_bfloat16* __restrict__ X0, const __nv_bfloat16* __restrict__ X1,
    const __nv_bfloat16* __restrict__ X2,
    void* C0, void* C1, void* C2, const float* __restrict__ bias)
{
    extern __shared__ char smem[];
    const uint32_t sb = smem_u32(smem);

    int b; bool elu; int which = 0;
    const __nv_bfloat16 *A, *B; OutT* C;
    if (PROJ) {
        which = blockIdx.z >> 3; b = blockIdx.z & 7;
        A = (which == 0) ? A0 : (which == 1) ? A1 : A2;
        B = (which == 0) ? X0 : (which == 1) ? X1 : X2;
        C = (OutT*)((which == 0) ? C0 : (which == 1) ? C1 : C2);
        elu = (which < 2);
    } else {
        b = blockIdx.z; A = A0; B = X0; C = (OutT*)C0; elu = false;
    }

    const int m0 = blockIdx.y * 128, n0 = blockIdx.x * 128;
    const __nv_bfloat16* Bb = B + (size_t)b * CH * NTOK;
    OutT* Cb = C + (size_t)b * CH * NTOK;

    const int tid = threadIdx.x;
    const int lane = tid & 31, wid = tid >> 5;
    const int wm = wid & 3, wn = wid >> 2;
    const int gr = lane >> 2, kc = lane & 3;

    const int lr = tid >> 3;
    const int lc = (tid & 7) * 2;
    const int swz = lr & 7;

    const int klow = ((lane >> 3) & 1) * 8 + (lane & 7);
    const int cg   = lane >> 4;

    float acc[2][8][4];
#pragma unroll
    for (int i = 0; i < 2; i++)
#pragma unroll
        for (int j = 0; j < 8; j++)
#pragma unroll
            for (int r = 0; r < 4; r++) acc[i][j][r] = 0.f;

    auto issue = [&](int kt, int s) {
        const __nv_bfloat16* pa = A  + (size_t)(kt * 32 + lr) * CH   + m0 + lc * 8;
        const __nv_bfloat16* pb = Bb + (size_t)(kt * 32 + lr) * NTOK + n0 + lc * 8;
        const uint32_t base = sb + s * STG_SZ + lr * 256;
        CP16(base + ((lc     ^ swz) * 16),        pa);
        CP16(base + (((lc+1) ^ swz) * 16),        pa + 8);
        CP16(base + ((lc     ^ swz) * 16) + 8192, pb);
        CP16(base + (((lc+1) ^ swz) * 16) + 8192, pb + 8);
    };

#pragma unroll
    for (int s = 0; s < 3; s++) { issue(s, s); CP_COMMIT(); }

    const int KT = CH / 32;  // 16
#pragma unroll 1
    for (int kt = 0; kt < KT; ++kt) {
        CP_WAIT(2);
        __syncthreads();
        const int s = kt & 3;
        const uint32_t stA = sb + s * STG_SZ;

#pragma unroll
        for (int ks = 0; ks < 2; ++ks) {
            const int krow = ks * 16 + klow;
            const int kx = krow & 7;
            const uint32_t rb = stA + krow * 256;

            uint32_t af[2][4];
#pragma unroll
            for (int i = 0; i < 2; i++) {
                const int mc = wm * 4 + i * 2 + cg;
                uint32_t r[4];
                ldsm_x4_t(r, rb + ((mc ^ kx) * 16));
                af[i][0] = r[0]; af[i][1] = r[2]; af[i][2] = r[1]; af[i][3] = r[3];
            }
            uint32_t bf[8][2];
#pragma unroll
            for (int jj = 0; jj < 4; jj++) {
                const int nc = wn * 8 + jj * 2 + cg;
                uint32_t r[4];
                ldsm_x4_t(r, rb + 8192 + ((nc ^ kx) * 16));
                bf[jj * 2][0]     = r[0];
                bf[jj * 2][1]     = r[1];
                bf[jj * 2 + 1][0] = r[2];
                bf[jj * 2 + 1][1] = r[3];
            }
#pragma unroll
            for (int i = 0; i < 2; i++)
#pragma unroll
                for (int j = 0; j < 8; j++)
                    mma_bf16(acc[i][j], af[i], bf[j]);
        }

        if (kt + 3 < KT) issue(kt + 3, (kt + 3) & 3);
        CP_COMMIT();
    }

    // epilogue (+ fused Ksum for which==1)
#pragma unroll
    for (int i = 0; i < 2; i++) {
        const int row = m0 + wm * 32 + i * 16 + gr;
        const float bi0 = BIAS ? bias[row] : 0.f;
        const float bi1 = BIAS ? bias[row + 8] : 0.f;
        float rs0 = 0.f, rs1 = 0.f;
#pragma unroll
        for (int j = 0; j < 8; j++) {
            const int col = n0 + wn * 64 + j * 8 + kc * 2;
            float c0 = acc[i][j][0], c1 = acc[i][j][1];
            float c2 = acc[i][j][2], c3 = acc[i][j][3];
            if (PROJ && elu) {
                c0 = (c0 > 0.f) ? (c0 + 1.f) : __expf(c0);
                c1 = (c1 > 0.f) ? (c1 + 1.f) : __expf(c1);
                c2 = (c2 > 0.f) ? (c2 + 1.f) : __expf(c2);
                c3 = (c3 > 0.f) ? (c3 + 1.f) : __expf(c3);
            }
            if (BIAS) { c0 += bi0; c1 += bi0; c2 += bi1; c3 += bi1; }
            if (PROJ && which == 1) { rs0 += c0 + c1; rs1 += c2 + c3; }
            if constexpr (sizeof(OutT) == 2) {
                *(__nv_bfloat162*)&Cb[(size_t)row * NTOK + col] =
                    __float22bfloat162_rn(make_float2(c0, c1));
                *(__nv_bfloat162*)&Cb[(size_t)(row + 8) * NTOK + col] =
                    __float22bfloat162_rn(make_float2(c2, c3));
            } else {
                *(float2*)&Cb[(size_t)row * NTOK + col]       = make_float2(c0, c1);
                *(float2*)&Cb[(size_t)(row + 8) * NTOK + col] = make_float2(c2, c3);
            }
        }
        if (PROJ && which == 1) {
            rs0 += __shfl_xor_sync(0xffffffffu, rs0, 1);
            rs0 += __shfl_xor_sync(0xffffffffu, rs0, 2);
            rs1 += __shfl_xor_sync(0xffffffffu, rs1, 1);
            rs1 += __shfl_xor_sync(0xffffffffu, rs1, 2);
            if (kc == 0) {
                atomicAdd(&g_Ksum[b * CH + row],     rs0);
                atomicAdd(&g_Ksum[b * CH + row + 8], rs1);
            }
        }
    }
}

// =====================================================================
// Middle stage: per token S=QK^T, Z=1/(Q.Ksum+eps), O=diag(Z) S V -> g_M [c][n]
// TN=16 tokens/block, 256 threads. Padded float4-friendly smem layout.
// =====================================================================
#define TN    16
#define SD    36                 // floats per d-row (32 + 4 pad), 16B aligned
#define TOKF  (16 * SD)          // 576 floats per token matrix
#define SSD   20                 // S row stride
#define SST   (16 * SSD)         // 320 floats per token S
#define MID_SMEM ((2 * TN * TOKF + TN * SST + TN * 20 + 16 * SD) * 4)

__global__ __launch_bounds__(256) void mid_kernel()
{
    extern __shared__ float sm[];
    float* buf0 = sm;                       // K, later O
    float* buf1 = buf0 + TN * TOKF;         // Q, later V
    float* Ss   = buf1 + TN * TOKF;
    float* Zs   = Ss + TN * SST;
    float* Ksm  = Zs + TN * 20;

    const int blk = blockIdx.x;
    const int b   = blk >> 8;
    const int n0  = (blk & 255) * TN;
    const size_t base = (size_t)b * CH * NTOK + n0;
    const int tid = threadIdx.x;

    for (int i = tid; i < CH; i += 256)
        Ksm[(i >> 5) * SD + (i & 31)] = g_Ksum[b * CH + i];

    for (int i = tid; i < CH * TN; i += 256) {
        const int tn = i & (TN - 1);
        const int c  = i >> 4;
        const int off = tn * TOKF + (c >> 5) * SD + (c & 31);
        buf0[off] = __bfloat162float(g_K[base + (size_t)c * NTOK + tn]);
        buf1[off] = __bfloat162float(g_Q[base + (size_t)c * NTOK + tn]);
    }
    __syncthreads();

    const int w    = tid >> 5;
    const int lane = tid & 31;
    const int hp   = lane & 15;
    const int half = lane >> 4;

#pragma unroll
    for (int tt = 0; tt < 2; ++tt) {
        const int t = w * 2 + tt;
        const float4* K4 = (const float4*)(buf0 + t * TOKF);
        const float4* Q4 = (const float4*)(buf1 + t * TOKF);
        float4 kc4[8];
#pragma unroll
        for (int j = 0; j < 8; j++) kc4[j] = K4[hp * 9 + j];
#pragma unroll
        for (int hi = 0; hi < 8; hi++) {
            const int h = half * 8 + hi;
            const float4* Qr = Q4 + h * 9;
            float s = 0.f;
#pragma unroll
            for (int j = 0; j < 8; j++) {
                float4 qv = Qr[j];
                s = fmaf(qv.x, kc4[j].x, s);
                s = fmaf(qv.y, kc4[j].y, s);
                s = fmaf(qv.z, kc4[j].z, s);
                s = fmaf(qv.w, kc4[j].w, s);
            }
            Ss[t * SST + h * SSD + hp] = s;
        }
        if (half == 0) {
            const float4* Qh = Q4 + hp * 9;
            const float4* Km = (const float4*)Ksm + hp * 9;
            float dn = 0.f;
#pragma unroll
            for (int j = 0; j < 8; j++) {
                float4 qv = Qh[j], kv = Km[j];
                dn = fmaf(qv.x, kv.x, dn);
                dn = fmaf(qv.y, kv.y, dn);
                dn = fmaf(qv.z, kv.z, dn);
                dn = fmaf(qv.w, kv.w, dn);
            }
            Zs[t * 20 + hp] = 1.f / (dn + 1e-5f);
        }
    }
    __syncthreads();

    for (int i = tid; i < CH * TN; i += 256) {
        const int tn = i & (TN - 1);
        const int c  = i >> 4;
        buf1[tn * TOKF + (c >> 5) * SD + (c & 31)] =
            __bfloat162float(g_V[base + (size_t)c * NTOK + tn]);
    }
    __syncthreads();

#pragma unroll
    for (int tt = 0; tt < 2; ++tt) {
        const int t = w * 2 + tt;
        const float* Vt = buf1 + t * TOKF;
        float vcol[16];
#pragma unroll
        for (int h = 0; h < 16; h++) vcol[h] = Vt[h * SD + lane];
#pragma unroll
        for (int h = 0; h < 16; h++) {
            const float4* Sr = (const float4*)(Ss + t * SST + h * SSD);
            float a = 0.f;
#pragma unroll
            for (int j = 0; j < 4; j++) {
                float4 sv = Sr[j];
                a = fmaf(sv.x, vcol[4 * j],     a);
                a = fmaf(sv.y, vcol[4 * j + 1], a);
                a = fmaf(sv.z, vcol[4 * j + 2], a);
                a = fmaf(sv.w, vcol[4 * j + 3], a);
            }
            buf0[t * TOKF + h * SD + lane] = a * Zs[t * 20 + h];
        }
    }
    __syncthreads();

    for (int i = tid; i < CH * TN; i += 256) {
        const int tn = i & (TN - 1);
        const int c  = i >> 4;
        g_M[base + (size_t)c * NTOK + tn] =
            __float2bfloat16(buf0[tn * TOKF + (c >> 5) * SD + (c & 31)]);
    }
}

// =====================================================================
extern "C" void kernel_launch(void* const* d_in, const int* in_sizes, int n_in,
                              void* d_out, int out_size)
{
    (void)in_sizes; (void)n_in; (void)out_size;
    const float* q  = (const float*)d_in[0];
    const float* k  = (const float*)d_in[1];
    const float* v  = (const float*)d_in[2];
    const float* Wq = (const float*)d_in[3];
    const float* Wk = (const float*)d_in[4];
    const float* Wv = (const float*)d_in[5];
    const float* Wp = (const float*)d_in[6];
    const float* bp = (const float*)d_in[7];
    float* out = (float*)d_out;

    void *wt, *x, *Qp, *Kp, *Vp, *Mp;
    cudaGetSymbolAddress(&wt, g_Wt);
    cudaGetSymbolAddress(&x,  g_X);
    cudaGetSymbolAddress(&Qp, g_Q);
    cudaGetSymbolAddress(&Kp, g_K);
    cudaGetSymbolAddress(&Vp, g_V);
    cudaGetSymbolAddress(&Mp, g_M);
    __nv_bfloat16* Wt = (__nv_bfloat16*)wt;
    __nv_bfloat16* X  = (__nv_bfloat16*)x;
    const size_t XS = (size_t)BATCH * CH * NTOK;

    cudaFuncSetAttribute(gemm_ca<true,  __nv_bfloat16, false>,
                         cudaFuncAttributeMaxDynamicSharedMemorySize, GEMM_SMEM);
    cudaFuncSetAttribute(gemm_ca<false, float, true>,
                         cudaFuncAttributeMaxDynamicSharedMemorySize, GEMM_SMEM);
    cudaFuncSetAttribute(mid_kernel,
                         cudaFuncAttributeMaxDynamicSharedMemorySize, MID_SMEM);

    // 1. prep (wprep also zeroes g_Ksum)
    wprep<<<dim3(16, 16, 4), 256>>>(Wq, Wk, Wv, Wp, Wt);
    xconv<<<dim3(8192, 1, 3), 256>>>((const float4*)q, (const float4*)k,
                                     (const float4*)v, (uint4*)X);

    // 2. projections (fused 3-in-1; K-proj accumulates Ksum via atomics)
    dim3 gp(NTOK / 128, CH / 128, 3 * BATCH);
    gemm_ca<true, __nv_bfloat16, false><<<gp, 256, GEMM_SMEM>>>(
        Wt, Wt + CH * CH, Wt + 2 * CH * CH,
        X, X + XS, X + 2 * XS,
        Qp, Kp, Vp, nullptr);

    // 3. middle
    mid_kernel<<<BATCH * (NTOK / TN), 256, MID_SMEM>>>();

    // 4. output projection
    dim3 gf(NTOK / 128, CH / 128, BATCH);
    gemm_ca<false, float, true><<<gf, 256, GEMM_SMEM>>>(
        Wt + 3 * CH * CH, nullptr, nullptr,
        (__nv_bfloat16*)Mp, nullptr, nullptr,
        out, nullptr, nullptr, bp);
}

// round 7
// speedup vs baseline: 1.0965x; 1.0965x over previous
#include <cuda_runtime.h>
#include <cuda_bf16.h>
#include <cstdint>
#include <cmath>

#define BATCH 8
#define CH    512
#define NTOK  4096

// ---------------- scratch (device globals) ----------------
__device__ __nv_bfloat16 g_Wt[4 * CH * CH];           // transposed bf16 weights [c][d]
__device__ __nv_bfloat16 g_X [3 * BATCH * CH * NTOK]; // bf16 q,k,v in [b][c][n]
__device__ __nv_bfloat16 g_Q [BATCH * CH * NTOK];
__device__ __nv_bfloat16 g_K [BATCH * CH * NTOK];
__device__ __nv_bfloat16 g_V [BATCH * CH * NTOK];
__device__ __nv_bfloat16 g_M [BATCH * CH * NTOK];
__device__ float g_Ksum[BATCH * CH];

// ---------------- helpers ----------------
__device__ __forceinline__ uint32_t smem_u32(const void* p) {
    uint32_t a;
    asm("{ .reg .u64 t; cvta.to.shared.u64 t, %1; cvt.u32.u64 %0, t; }" : "=r"(a) : "l"(p));
    return a;
}
__device__ __forceinline__ uint32_t bf2u(__nv_bfloat162 h) {
    union { __nv_bfloat162 h; uint32_t u; } z; z.h = h; return z.u;
}
__device__ __forceinline__ void mma_bf16(float c[4], const uint32_t a[4], const uint32_t b[2]) {
    asm volatile(
        "mma.sync.aligned.m16n8k16.row.col.f32.bf16.bf16.f32 "
        "{%0,%1,%2,%3}, {%4,%5,%6,%7}, {%8,%9}, {%0,%1,%2,%3};"
        : "+f"(c[0]), "+f"(c[1]), "+f"(c[2]), "+f"(c[3])
        : "r"(a[0]), "r"(a[1]), "r"(a[2]), "r"(a[3]), "r"(b[0]), "r"(b[1]));
}
__device__ __forceinline__ void ldsm_x4_t(uint32_t r[4], uint32_t addr) {
    asm volatile("ldmatrix.sync.aligned.m8n8.x4.trans.shared.b16 {%0,%1,%2,%3}, [%4];"
                 : "=r"(r[0]), "=r"(r[1]), "=r"(r[2]), "=r"(r[3]) : "r"(addr));
}
#define CP16(dst, src) \
    asm volatile("cp.async.cg.shared.global [%0], [%1], 16;" :: "r"(dst), "l"(src) : "memory")
#define CP_COMMIT() asm volatile("cp.async.commit_group;" ::: "memory")
#define CP_WAIT(n)  asm volatile("cp.async.wait_group %0;" :: "n"(n) : "memory")

// =====================================================================
// weight prep: W fp32 [d][c] -> bf16 [c][d]  (grid 16,16,4); also zeros g_Ksum
// =====================================================================
__global__ __launch_bounds__(256) void wprep(
    const float* __restrict__ W0, const float* __restrict__ W1,
    const float* __restrict__ W2, const float* __restrict__ W3,
    __nv_bfloat16* __restrict__ D)
{
    __shared__ float t[32][33];
    if (blockIdx.z == 0 && blockIdx.y == 0)
        g_Ksum[blockIdx.x * 256 + threadIdx.x] = 0.f;
    const int z = blockIdx.z;
    const float* S = (z == 0) ? W0 : (z == 1) ? W1 : (z == 2) ? W2 : W3;
    __nv_bfloat16* Dz = D + (size_t)z * CH * CH;
    const int d0 = blockIdx.x * 32, c0 = blockIdx.y * 32;
    const int x = threadIdx.x & 31, y = threadIdx.x >> 5;
#pragma unroll
    for (int i = 0; i < 4; i++)
        t[y + 8 * i][x] = S[(size_t)(d0 + y + 8 * i) * CH + c0 + x];
    __syncthreads();
    const int m2 = threadIdx.x & 15, r0 = threadIdx.x >> 4;
#pragma unroll
    for (int i = 0; i < 2; i++) {
        const int r = r0 + 16 * i;
        __nv_bfloat162 h = __float22bfloat162_rn(make_float2(t[m2 * 2][r], t[m2 * 2 + 1][r]));
        *(__nv_bfloat162*)&Dz[(size_t)(c0 + r) * CH + d0 + m2 * 2] = h;
    }
}

// =====================================================================
// input prep: fp32 -> bf16 elementwise (grid 8192,1,3)
// =====================================================================
__global__ __launch_bounds__(256) void xconv(
    const float4* __restrict__ s0, const float4* __restrict__ s1,
    const float4* __restrict__ s2, uint4* __restrict__ d)
{
    const int z = blockIdx.z;
    const float4* s = (z == 0) ? s0 : (z == 1) ? s1 : s2;
    uint4* dz = d + (size_t)z * (BATCH * CH * NTOK / 8);
    const size_t i = (size_t)blockIdx.x * 256 + threadIdx.x;
    float4 a = s[2 * i], b = s[2 * i + 1];
    uint4 o;
    o.x = bf2u(__float22bfloat162_rn(make_float2(a.x, a.y)));
    o.y = bf2u(__float22bfloat162_rn(make_float2(a.z, a.w)));
    o.z = bf2u(__float22bfloat162_rn(make_float2(b.x, b.y)));
    o.w = bf2u(__float22bfloat162_rn(make_float2(b.z, b.w)));
    dz[i] = o;
}

// =====================================================================
// GEMM: C[b,d,n] = sum_c At[c,d] * B[b,c,n]  (+elu+1 | +bias | +ksum atomics)
// BM=BN=128, BK=32, 4-stage cp.async, 256 thr, 8 warps (4m x 2n), 32x64.
// =====================================================================
#define STG_SZ 16384
#define GEMM_SMEM (4 * STG_SZ)

template<bool PROJ, typename OutT, bool BIAS>
__global__ __launch_bounds__(256, 2) void gemm_ca(
    const __nv_bfloat16* __restrict__ A0, const __nv_bfloat16* __restrict__ A1,
    const __nv_bfloat16* __restrict__ A2,
    const __nv_bfloat16* __restrict__ X0, const __nv_bfloat16* __restrict__ X1,
    const __nv_bfloat16* __restrict__ X2,
    void* C0, void* C1, void* C2, const float* __restrict__ bias)
{
    extern __shared__ char smem[];
    const uint32_t sb = smem_u32(smem);

    int b; bool elu; int which = 0;
    const __nv_bfloat16 *A, *B; OutT* C;
    if (PROJ) {
        which = blockIdx.z >> 3; b = blockIdx.z & 7;
        A = (which == 0) ? A0 : (which == 1) ? A1 : A2;
        B = (which == 0) ? X0 : (which == 1) ? X1 : X2;
        C = (OutT*)((which == 0) ? C0 : (which == 1) ? C1 : C2);
        elu = (which < 2);
    } else {
        b = blockIdx.z; A = A0; B = X0; C = (OutT*)C0; elu = false;
    }

    const int m0 = blockIdx.y * 128, n0 = blockIdx.x * 128;
    const __nv_bfloat16* Bb = B + (size_t)b * CH * NTOK;
    OutT* Cb = C + (size_t)b * CH * NTOK;

    const int tid = threadIdx.x;
    const int lane = tid & 31, wid = tid >> 5;
    const int wm = wid & 3, wn = wid >> 2;
    const int gr = lane >> 2, kc = lane & 3;

    const int lr = tid >> 3;
    const int lc = (tid & 7) * 2;
    const int swz = lr & 7;

    const int klow = ((lane >> 3) & 1) * 8 + (lane & 7);
    const int cg   = lane >> 4;

    float acc[2][8][4];
#pragma unroll
    for (int i = 0; i < 2; i++)
#pragma unroll
        for (int j = 0; j < 8; j++)
#pragma unroll
            for (int r = 0; r < 4; r++) acc[i][j][r] = 0.f;

    auto issue = [&](int kt, int s) {
        const __nv_bfloat16* pa = A  + (size_t)(kt * 32 + lr) * CH   + m0 + lc * 8;
        const __nv_bfloat16* pb = Bb + (size_t)(kt * 32 + lr) * NTOK + n0 + lc * 8;
        const uint32_t base = sb + s * STG_SZ + lr * 256;
        CP16(base + ((lc     ^ swz) * 16),        pa);
        CP16(base + (((lc+1) ^ swz) * 16),        pa + 8);
        CP16(base + ((lc     ^ swz) * 16) + 8192, pb);
        CP16(base + (((lc+1) ^ swz) * 16) + 8192, pb + 8);
    };

#pragma unroll
    for (int s = 0; s < 3; s++) { issue(s, s); CP_COMMIT(); }

    const int KT = CH / 32;  // 16
#pragma unroll 1
    for (int kt = 0; kt < KT; ++kt) {
        CP_WAIT(2);
        __syncthreads();
        const int s = kt & 3;
        const uint32_t stA = sb + s * STG_SZ;

#pragma unroll
        for (int ks = 0; ks < 2; ++ks) {
            const int krow = ks * 16 + klow;
            const int kx = krow & 7;
            const uint32_t rb = stA + krow * 256;

            uint32_t af[2][4];
#pragma unroll
            for (int i = 0; i < 2; i++) {
                const int mc = wm * 4 + i * 2 + cg;
                uint32_t r[4];
                ldsm_x4_t(r, rb + ((mc ^ kx) * 16));
                af[i][0] = r[0]; af[i][1] = r[2]; af[i][2] = r[1]; af[i][3] = r[3];
            }
            uint32_t bf[8][2];
#pragma unroll
            for (int jj = 0; jj < 4; jj++) {
                const int nc = wn * 8 + jj * 2 + cg;
                uint32_t r[4];
                ldsm_x4_t(r, rb + 8192 + ((nc ^ kx) * 16));
                bf[jj * 2][0]     = r[0];
                bf[jj * 2][1]     = r[1];
                bf[jj * 2 + 1][0] = r[2];
                bf[jj * 2 + 1][1] = r[3];
            }
#pragma unroll
            for (int i = 0; i < 2; i++)
#pragma unroll
                for (int j = 0; j < 8; j++)
                    mma_bf16(acc[i][j], af[i], bf[j]);
        }

        if (kt + 3 < KT) issue(kt + 3, (kt + 3) & 3);
        CP_COMMIT();
    }

    // epilogue (+ fused Ksum for which==1)
#pragma unroll
    for (int i = 0; i < 2; i++) {
        const int row = m0 + wm * 32 + i * 16 + gr;
        const float bi0 = BIAS ? bias[row] : 0.f;
        const float bi1 = BIAS ? bias[row + 8] : 0.f;
        float rs0 = 0.f, rs1 = 0.f;
#pragma unroll
        for (int j = 0; j < 8; j++) {
            const int col = n0 + wn * 64 + j * 8 + kc * 2;
            float c0 = acc[i][j][0], c1 = acc[i][j][1];
            float c2 = acc[i][j][2], c3 = acc[i][j][3];
            if (PROJ && elu) {
                c0 = (c0 > 0.f) ? (c0 + 1.f) : __expf(c0);
                c1 = (c1 > 0.f) ? (c1 + 1.f) : __expf(c1);
                c2 = (c2 > 0.f) ? (c2 + 1.f) : __expf(c2);
                c3 = (c3 > 0.f) ? (c3 + 1.f) : __expf(c3);
            }
            if (BIAS) { c0 += bi0; c1 += bi0; c2 += bi1; c3 += bi1; }
            if (PROJ && which == 1) { rs0 += c0 + c1; rs1 += c2 + c3; }
            if constexpr (sizeof(OutT) == 2) {
                *(__nv_bfloat162*)&Cb[(size_t)row * NTOK + col] =
                    __float22bfloat162_rn(make_float2(c0, c1));
                *(__nv_bfloat162*)&Cb[(size_t)(row + 8) * NTOK + col] =
                    __float22bfloat162_rn(make_float2(c2, c3));
            } else {
                *(float2*)&Cb[(size_t)row * NTOK + col]       = make_float2(c0, c1);
                *(float2*)&Cb[(size_t)(row + 8) * NTOK + col] = make_float2(c2, c3);
            }
        }
        if (PROJ && which == 1) {
            rs0 += __shfl_xor_sync(0xffffffffu, rs0, 1);
            rs0 += __shfl_xor_sync(0xffffffffu, rs0, 2);
            rs1 += __shfl_xor_sync(0xffffffffu, rs1, 1);
            rs1 += __shfl_xor_sync(0xffffffffu, rs1, 2);
            if (kc == 0) {
                atomicAdd(&g_Ksum[b * CH + row],     rs0);
                atomicAdd(&g_Ksum[b * CH + row + 8], rs1);
            }
        }
    }
}

// =====================================================================
// Middle stage: per token S=QK^T, Z=1/(Q.Ksum+eps), O=diag(Z) S V -> g_M [c][n]
// TN=8 tokens/block, 256 threads (8 warps x 1 token).
// Conflict-free layout: strides 33 (rows) / 529 (tokens) / 273 (S) — odd mod 32.
// Wide I/O: one uint4 = 8 tokens per thread per c-row.
// =====================================================================
#define TN    8
#define TOKP  529
#define SSTR  273
#define MID_SMEM ((2 * TN * TOKP + TN * SSTR + TN * 17 + 16 * 33) * 4)

__global__ __launch_bounds__(256) void mid_kernel()
{
    extern __shared__ float sm[];
    float* buf0 = sm;                        // K, later O
    float* buf1 = buf0 + TN * TOKP;          // Q, later V
    float* Ss   = buf1 + TN * TOKP;
    float* Zs   = Ss + TN * SSTR;
    float* Ksm  = Zs + TN * 17;

    const int blk = blockIdx.x;              // BATCH * 512
    const int b   = blk >> 9;
    const int n0  = (blk & 511) * TN;
    const size_t base = (size_t)b * CH * NTOK + n0;
    const int tid = threadIdx.x;

    for (int i = tid; i < CH; i += 256)
        Ksm[(i >> 5) * 33 + (i & 31)] = g_Ksum[b * CH + i];

    // wide load: thread handles c-row i, all 8 tokens (one uint4) for K and Q
    for (int c = tid; c < CH; c += 256) {
        const int off = (c >> 5) * 33 + (c & 31);
        uint4 ku = *(const uint4*)&g_K[base + (size_t)c * NTOK];
        uint4 qu = *(const uint4*)&g_Q[base + (size_t)c * NTOK];
        const __nv_bfloat162* kh = (const __nv_bfloat162*)&ku;
        const __nv_bfloat162* qh = (const __nv_bfloat162*)&qu;
#pragma unroll
        for (int j = 0; j < 4; j++) {
            float2 kf = __bfloat1622float2(kh[j]);
            float2 qf = __bfloat1622float2(qh[j]);
            buf0[(2 * j)     * TOKP + off] = kf.x;
            buf0[(2 * j + 1) * TOKP + off] = kf.y;
            buf1[(2 * j)     * TOKP + off] = qf.x;
            buf1[(2 * j + 1) * TOKP + off] = qf.y;
        }
    }
    __syncthreads();

    const int w    = tid >> 5;       // warp = token 0..7
    const int lane = tid & 31;
    const int hp   = lane & 15;
    const int half = lane >> 4;

    // Phase A: S = Q K^T, Z = 1/(Q.Ksum + eps)
    {
        const int t = w;
        const float* Kt = &buf0[t * TOKP];
        const float* Qt = &buf1[t * TOKP];
        float kcol[32];
#pragma unroll
        for (int d = 0; d < 32; d++) kcol[d] = Kt[hp * 33 + d];
#pragma unroll
        for (int hi = 0; hi < 8; hi++) {
            const int h = half * 8 + hi;
            float s = 0.f;
#pragma unroll
            for (int d = 0; d < 32; d++) s = fmaf(Qt[h * 33 + d], kcol[d], s);
            Ss[t * SSTR + h * 17 + hp] = s;
        }
        if (half == 0) {
            float dn = 0.f;
#pragma unroll
            for (int d = 0; d < 32; d++) dn = fmaf(Qt[hp * 33 + d], Ksm[hp * 33 + d], dn);
            Zs[t * 17 + hp] = 1.f / (dn + 1e-5f);
        }
    }
    __syncthreads();

    // wide load V -> buf1 (overwrites Q)
    for (int c = tid; c < CH; c += 256) {
        const int off = (c >> 5) * 33 + (c & 31);
        uint4 vu = *(const uint4*)&g_V[base + (size_t)c * NTOK];
        const __nv_bfloat162* vh = (const __nv_bfloat162*)&vu;
#pragma unroll
        for (int j = 0; j < 4; j++) {
            float2 vf = __bfloat1622float2(vh[j]);
            buf1[(2 * j)     * TOKP + off] = vf.x;
            buf1[(2 * j + 1) * TOKP + off] = vf.y;
        }
    }
    __syncthreads();

    // Phase B: O = diag(Z) S V -> buf0
    {
        const int t = w;
        const float* Vt = &buf1[t * TOKP];
        float vcol[16];
#pragma unroll
        for (int h = 0; h < 16; h++) vcol[h] = Vt[h * 33 + lane];
#pragma unroll
        for (int h = 0; h < 16; h++) {
            float a = 0.f;
#pragma unroll
            for (int q = 0; q < 16; q++) a = fmaf(Ss[t * SSTR + h * 17 + q], vcol[q], a);
            buf0[t * TOKP + h * 33 + lane] = a * Zs[t * 17 + h];
        }
    }
    __syncthreads();

    // wide store: pack 8 tokens per c-row into one uint4
    for (int c = tid; c < CH; c += 256) {
        const int off = (c >> 5) * 33 + (c & 31);
        uint4 o;
        uint32_t* o32 = (uint32_t*)&o;
#pragma unroll
        for (int j = 0; j < 4; j++) {
            float2 f = make_float2(buf0[(2 * j) * TOKP + off],
                                   buf0[(2 * j + 1) * TOKP + off]);
            o32[j] = bf2u(__float22bfloat162_rn(f));
        }
        *(uint4*)&g_M[base + (size_t)c * NTOK] = o;
    }
}

// =====================================================================
extern "C" void kernel_launch(void* const* d_in, const int* in_sizes, int n_in,
                              void* d_out, int out_size)
{
    (void)in_sizes; (void)n_in; (void)out_size;
    const float* q  = (const float*)d_in[0];
    const float* k  = (const float*)d_in[1];
    const float* v  = (const float*)d_in[2];
    const float* Wq = (const float*)d_in[3];
    const float* Wk = (const float*)d_in[4];
    const float* Wv = (const float*)d_in[5];
    const float* Wp = (const float*)d_in[6];
    const float* bp = (const float*)d_in[7];
    float* out = (float*)d_out;

    void *wt, *x, *Qp, *Kp, *Vp, *Mp;
    cudaGetSymbolAddress(&wt, g_Wt);
    cudaGetSymbolAddress(&x,  g_X);
    cudaGetSymbolAddress(&Qp, g_Q);
    cudaGetSymbolAddress(&Kp, g_K);
    cudaGetSymbolAddress(&Vp, g_V);
    cudaGetSymbolAddress(&Mp, g_M);
    __nv_bfloat16* Wt = (__nv_bfloat16*)wt;
    __nv_bfloat16* X  = (__nv_bfloat16*)x;
    const size_t XS = (size_t)BATCH * CH * NTOK;

    cudaFuncSetAttribute(gemm_ca<true,  __nv_bfloat16, false>,
                         cudaFuncAttributeMaxDynamicSharedMemorySize, GEMM_SMEM);
    cudaFuncSetAttribute(gemm_ca<false, float, true>,
                         cudaFuncAttributeMaxDynamicSharedMemorySize, GEMM_SMEM);
    cudaFuncSetAttribute(mid_kernel,
                         cudaFuncAttributeMaxDynamicSharedMemorySize, MID_SMEM);

    // 1. prep (wprep also zeroes g_Ksum)
    wprep<<<dim3(16, 16, 4), 256>>>(Wq, Wk, Wv, Wp, Wt);
    xconv<<<dim3(8192, 1, 3), 256>>>((const float4*)q, (const float4*)k,
                                     (const float4*)v, (uint4*)X);

    // 2. projections (fused 3-in-1; K-proj accumulates Ksum via atomics)
    dim3 gp(NTOK / 128, CH / 128, 3 * BATCH);
    gemm_ca<true, __nv_bfloat16, false><<<gp, 256, GEMM_SMEM>>>(
        Wt, Wt + CH * CH, Wt + 2 * CH * CH,
        X, X + XS, X + 2 * XS,
        Qp, Kp, Vp, nullptr);

    // 3. middle
    mid_kernel<<<BATCH * (NTOK / TN), 256, MID_SMEM>>>();

    // 4. output projection
    dim3 gf(NTOK / 128, CH / 128, BATCH);
    gemm_ca<false, float, true><<<gf, 256, GEMM_SMEM>>>(
        Wt + 3 * CH * CH, nullptr, nullptr,
        (__nv_bfloat16*)Mp, nullptr, nullptr,
        out, nullptr, nullptr, bp);
}

// round 8
// speedup vs baseline: 1.2483x; 1.1385x over previous
#include <cuda_runtime.h>
#include <cuda_bf16.h>
#include <cstdint>
#include <cmath>

#define BATCH 8
#define CH    512
#define NTOK  4096

// ---------------- scratch (device globals) ----------------
__device__ __nv_bfloat16 g_Wt[4 * CH * CH];           // transposed bf16 weights [c][d]
__device__ __nv_bfloat16 g_X [3 * BATCH * CH * NTOK]; // bf16 q,k,v in [b][c][n]
__device__ __nv_bfloat16 g_Q [BATCH * CH * NTOK];
__device__ __nv_bfloat16 g_K [BATCH * CH * NTOK];
__device__ __nv_bfloat16 g_V [BATCH * CH * NTOK];
__device__ __nv_bfloat16 g_M [BATCH * CH * NTOK];
__device__ float g_Ksum[BATCH * CH];

// ---------------- helpers ----------------
__device__ __forceinline__ uint32_t smem_u32(const void* p) {
    uint32_t a;
    asm("{ .reg .u64 t; cvta.to.shared.u64 t, %1; cvt.u32.u64 %0, t; }" : "=r"(a) : "l"(p));
    return a;
}
__device__ __forceinline__ uint32_t bf2u(__nv_bfloat162 h) {
    union { __nv_bfloat162 h; uint32_t u; } z; z.h = h; return z.u;
}
__device__ __forceinline__ void mma_bf16(float c[4], const uint32_t a[4], const uint32_t b[2]) {
    asm volatile(
        "mma.sync.aligned.m16n8k16.row.col.f32.bf16.bf16.f32 "
        "{%0,%1,%2,%3}, {%4,%5,%6,%7}, {%8,%9}, {%0,%1,%2,%3};"
        : "+f"(c[0]), "+f"(c[1]), "+f"(c[2]), "+f"(c[3])
        : "r"(a[0]), "r"(a[1]), "r"(a[2]), "r"(a[3]), "r"(b[0]), "r"(b[1]));
}
__device__ __forceinline__ void ldsm_x4_t(uint32_t r[4], uint32_t addr) {
    asm volatile("ldmatrix.sync.aligned.m8n8.x4.trans.shared.b16 {%0,%1,%2,%3}, [%4];"
                 : "=r"(r[0]), "=r"(r[1]), "=r"(r[2]), "=r"(r[3]) : "r"(addr));
}
#define CP16(dst, src) \
    asm volatile("cp.async.cg.shared.global [%0], [%1], 16;" :: "r"(dst), "l"(src) : "memory")
#define CP_COMMIT() asm volatile("cp.async.commit_group;" ::: "memory")
#define CP_WAIT(n)  asm volatile("cp.async.wait_group %0;" :: "n"(n) : "memory")

// packed f32x2 ops (sm_100+ base PTX)
__device__ __forceinline__ void fma2(unsigned long long& acc,
                                     unsigned long long a, unsigned long long b) {
    asm("fma.rn.f32x2 %0, %1, %2, %0;" : "+l"(acc) : "l"(a), "l"(b));
}
__device__ __forceinline__ unsigned long long pk2(float x, float y) {
    unsigned long long r;
    asm("mov.b64 %0, {%1, %2};" : "=l"(r) : "f"(x), "f"(y));
    return r;
}
__device__ __forceinline__ float hsum2(unsigned long long v) {
    float x, y;
    asm("mov.b64 {%0, %1}, %2;" : "=f"(x), "=f"(y) : "l"(v));
    return x + y;
}

// =====================================================================
// weight prep: W fp32 [d][c] -> bf16 [c][d]  (grid 16,16,4); also zeros g_Ksum
// =====================================================================
__global__ __launch_bounds__(256) void wprep(
    const float* __restrict__ W0, const float* __restrict__ W1,
    const float* __restrict__ W2, const float* __restrict__ W3,
    __nv_bfloat16* __restrict__ D)
{
    __shared__ float t[32][33];
    if (blockIdx.z == 0 && blockIdx.y == 0)
        g_Ksum[blockIdx.x * 256 + threadIdx.x] = 0.f;
    const int z = blockIdx.z;
    const float* S = (z == 0) ? W0 : (z == 1) ? W1 : (z == 2) ? W2 : W3;
    __nv_bfloat16* Dz = D + (size_t)z * CH * CH;
    const int d0 = blockIdx.x * 32, c0 = blockIdx.y * 32;
    const int x = threadIdx.x & 31, y = threadIdx.x >> 5;
#pragma unroll
    for (int i = 0; i < 4; i++)
        t[y + 8 * i][x] = S[(size_t)(d0 + y + 8 * i) * CH + c0 + x];
    __syncthreads();
    const int m2 = threadIdx.x & 15, r0 = threadIdx.x >> 4;
#pragma unroll
    for (int i = 0; i < 2; i++) {
        const int r = r0 + 16 * i;
        __nv_bfloat162 h = __float22bfloat162_rn(make_float2(t[m2 * 2][r], t[m2 * 2 + 1][r]));
        *(__nv_bfloat162*)&Dz[(size_t)(c0 + r) * CH + d0 + m2 * 2] = h;
    }
}

// =====================================================================
// input prep: fp32 -> bf16 elementwise (grid 8192,1,3)
// =====================================================================
__global__ __launch_bounds__(256) void xconv(
    const float4* __restrict__ s0, const float4* __restrict__ s1,
    const float4* __restrict__ s2, uint4* __restrict__ d)
{
    const int z = blockIdx.z;
    const float4* s = (z == 0) ? s0 : (z == 1) ? s1 : s2;
    uint4* dz = d + (size_t)z * (BATCH * CH * NTOK / 8);
    const size_t i = (size_t)blockIdx.x * 256 + threadIdx.x;
    float4 a = s[2 * i], b = s[2 * i + 1];
    uint4 o;
    o.x = bf2u(__float22bfloat162_rn(make_float2(a.x, a.y)));
    o.y = bf2u(__float22bfloat162_rn(make_float2(a.z, a.w)));
    o.z = bf2u(__float22bfloat162_rn(make_float2(b.x, b.y)));
    o.w = bf2u(__float22bfloat162_rn(make_float2(b.z, b.w)));
    dz[i] = o;
}

// =====================================================================
// GEMM: C[b,d,n] = sum_c At[c,d] * B[b,c,n]  (+elu+1 | +bias | +ksum atomics)
// BM=BN=128, BK=32, 4-stage cp.async, 256 thr, 8 warps (4m x 2n), 32x64.
// =====================================================================
#define STG_SZ 16384
#define GEMM_SMEM (4 * STG_SZ)

template<bool PROJ, typename OutT, bool BIAS>
__global__ __launch_bounds__(256, 2) void gemm_ca(
    const __nv_bfloat16* __restrict__ A0, const __nv_bfloat16* __restrict__ A1,
    const __nv_bfloat16* __restrict__ A2,
    const __nv_bfloat16* __restrict__ X0, const __nv_bfloat16* __restrict__ X1,
    const __nv_bfloat16* __restrict__ X2,
    void* C0, void* C1, void* C2, const float* __restrict__ bias)
{
    extern __shared__ char smem[];
    const uint32_t sb = smem_u32(smem);

    int b; bool elu; int which = 0;
    const __nv_bfloat16 *A, *B; OutT* C;
    if (PROJ) {
        which = blockIdx.z >> 3; b = blockIdx.z & 7;
        A = (which == 0) ? A0 : (which == 1) ? A1 : A2;
        B = (which == 0) ? X0 : (which == 1) ? X1 : X2;
        C = (OutT*)((which == 0) ? C0 : (which == 1) ? C1 : C2);
        elu = (which < 2);
    } else {
        b = blockIdx.z; A = A0; B = X0; C = (OutT*)C0; elu = false;
    }

    const int m0 = blockIdx.y * 128, n0 = blockIdx.x * 128;
    const __nv_bfloat16* Bb = B + (size_t)b * CH * NTOK;
    OutT* Cb = C + (size_t)b * CH * NTOK;

    const int tid = threadIdx.x;
    const int lane = tid & 31, wid = tid >> 5;
    const int wm = wid & 3, wn = wid >> 2;
    const int gr = lane >> 2, kc = lane & 3;

    const int lr = tid >> 3;
    const int lc = (tid & 7) * 2;
    const int swz = lr & 7;

    const int klow = ((lane >> 3) & 1) * 8 + (lane & 7);
    const int cg   = lane >> 4;

    float acc[2][8][4];
#pragma unroll
    for (int i = 0; i < 2; i++)
#pragma unroll
        for (int j = 0; j < 8; j++)
#pragma unroll
            for (int r = 0; r < 4; r++) acc[i][j][r] = 0.f;

    auto issue = [&](int kt, int s) {
        const __nv_bfloat16* pa = A  + (size_t)(kt * 32 + lr) * CH   + m0 + lc * 8;
        const __nv_bfloat16* pb = Bb + (size_t)(kt * 32 + lr) * NTOK + n0 + lc * 8;
        const uint32_t base = sb + s * STG_SZ + lr * 256;
        CP16(base + ((lc     ^ swz) * 16),        pa);
        CP16(base + (((lc+1) ^ swz) * 16),        pa + 8);
        CP16(base + ((lc     ^ swz) * 16) + 8192, pb);
        CP16(base + (((lc+1) ^ swz) * 16) + 8192, pb + 8);
    };

#pragma unroll
    for (int s = 0; s < 3; s++) { issue(s, s); CP_COMMIT(); }

    const int KT = CH / 32;  // 16
#pragma unroll 1
    for (int kt = 0; kt < KT; ++kt) {
        CP_WAIT(2);
        __syncthreads();
        const int s = kt & 3;
        const uint32_t stA = sb + s * STG_SZ;

#pragma unroll
        for (int ks = 0; ks < 2; ++ks) {
            const int krow = ks * 16 + klow;
            const int kx = krow & 7;
            const uint32_t rb = stA + krow * 256;

            uint32_t af[2][4];
#pragma unroll
            for (int i = 0; i < 2; i++) {
                const int mc = wm * 4 + i * 2 + cg;
                uint32_t r[4];
                ldsm_x4_t(r, rb + ((mc ^ kx) * 16));
                af[i][0] = r[0]; af[i][1] = r[2]; af[i][2] = r[1]; af[i][3] = r[3];
            }
            uint32_t bf[8][2];
#pragma unroll
            for (int jj = 0; jj < 4; jj++) {
                const int nc = wn * 8 + jj * 2 + cg;
                uint32_t r[4];
                ldsm_x4_t(r, rb + 8192 + ((nc ^ kx) * 16));
                bf[jj * 2][0]     = r[0];
                bf[jj * 2][1]     = r[1];
                bf[jj * 2 + 1][0] = r[2];
                bf[jj * 2 + 1][1] = r[3];
            }
#pragma unroll
            for (int i = 0; i < 2; i++)
#pragma unroll
                for (int j = 0; j < 8; j++)
                    mma_bf16(acc[i][j], af[i], bf[j]);
        }

        if (kt + 3 < KT) issue(kt + 3, (kt + 3) & 3);
        CP_COMMIT();
    }

    // epilogue (+ fused Ksum for which==1)
#pragma unroll
    for (int i = 0; i < 2; i++) {
        const int row = m0 + wm * 32 + i * 16 + gr;
        const float bi0 = BIAS ? bias[row] : 0.f;
        const float bi1 = BIAS ? bias[row + 8] : 0.f;
        float rs0 = 0.f, rs1 = 0.f;
#pragma unroll
        for (int j = 0; j < 8; j++) {
            const int col = n0 + wn * 64 + j * 8 + kc * 2;
            float c0 = acc[i][j][0], c1 = acc[i][j][1];
            float c2 = acc[i][j][2], c3 = acc[i][j][3];
            if (PROJ && elu) {
                c0 = (c0 > 0.f) ? (c0 + 1.f) : __expf(c0);
                c1 = (c1 > 0.f) ? (c1 + 1.f) : __expf(c1);
                c2 = (c2 > 0.f) ? (c2 + 1.f) : __expf(c2);
                c3 = (c3 > 0.f) ? (c3 + 1.f) : __expf(c3);
            }
            if (BIAS) { c0 += bi0; c1 += bi0; c2 += bi1; c3 += bi1; }
            if (PROJ && which == 1) { rs0 += c0 + c1; rs1 += c2 + c3; }
            if constexpr (sizeof(OutT) == 2) {
                *(__nv_bfloat162*)&Cb[(size_t)row * NTOK + col] =
                    __float22bfloat162_rn(make_float2(c0, c1));
                *(__nv_bfloat162*)&Cb[(size_t)(row + 8) * NTOK + col] =
                    __float22bfloat162_rn(make_float2(c2, c3));
            } else {
                *(float2*)&Cb[(size_t)row * NTOK + col]       = make_float2(c0, c1);
                *(float2*)&Cb[(size_t)(row + 8) * NTOK + col] = make_float2(c2, c3);
            }
        }
        if (PROJ && which == 1) {
            rs0 += __shfl_xor_sync(0xffffffffu, rs0, 1);
            rs0 += __shfl_xor_sync(0xffffffffu, rs0, 2);
            rs1 += __shfl_xor_sync(0xffffffffu, rs1, 1);
            rs1 += __shfl_xor_sync(0xffffffffu, rs1, 2);
            if (kc == 0) {
                atomicAdd(&g_Ksum[b * CH + row],     rs0);
                atomicAdd(&g_Ksum[b * CH + row + 8], rs1);
            }
        }
    }
}

// =====================================================================
// Middle stage: per token S=QK^T, Z=1/(Q.Ksum+eps), O=diag(Z) S V -> g_M [c][n]
// TN=8 tokens/block, 256 thr (1 token/warp). Packed f32x2 math + LDS.64.
// Row stride SD=36 floats (8/16B aligned), token stride 576; S stride 18.
// =====================================================================
#define TN    8
#define SD    36
#define TOKF  576            // 16 * 36
#define SSD   18
#define SST   288            // 16 * 18
#define MID_SMEM ((2 * TN * TOKF + TN * SST + TN * 18 + 16 * SD) * 4)

__global__ __launch_bounds__(256) void mid_kernel()
{
    extern __shared__ float sm[];
    float* buf0 = sm;                        // K, later O
    float* buf1 = buf0 + TN * TOKF;          // Q, later V
    float* Ss   = buf1 + TN * TOKF;
    float* Zs   = Ss + TN * SST;
    float* Ksm  = Zs + TN * 18;

    const int blk = blockIdx.x;              // BATCH * 512
    const int b   = blk >> 9;
    const int n0  = (blk & 511) * TN;
    const size_t base = (size_t)b * CH * NTOK + n0;
    const int tid = threadIdx.x;

    for (int i = tid; i < CH; i += 256)
        Ksm[(i >> 5) * SD + (i & 31)] = g_Ksum[b * CH + i];

    // wide load: thread handles c-row, 8 tokens (one uint4) for K and Q
    for (int c = tid; c < CH; c += 256) {
        const int off = (c >> 5) * SD + (c & 31);
        uint4 ku = *(const uint4*)&g_K[base + (size_t)c * NTOK];
        uint4 qu = *(const uint4*)&g_Q[base + (size_t)c * NTOK];
        const __nv_bfloat162* kh = (const __nv_bfloat162*)&ku;
        const __nv_bfloat162* qh = (const __nv_bfloat162*)&qu;
#pragma unroll
        for (int j = 0; j < 4; j++) {
            float2 kf = __bfloat1622float2(kh[j]);
            float2 qf = __bfloat1622float2(qh[j]);
            buf0[(2 * j)     * TOKF + off] = kf.x;
            buf0[(2 * j + 1) * TOKF + off] = kf.y;
            buf1[(2 * j)     * TOKF + off] = qf.x;
            buf1[(2 * j + 1) * TOKF + off] = qf.y;
        }
    }
    __syncthreads();

    const int w    = tid >> 5;       // warp = token
    const int lane = tid & 31;
    const int hp   = lane & 15;
    const int half = lane >> 4;
    const int t    = w;

    // Phase A: S = Q K^T (packed pairs), Z = 1/(Q.Ksum + eps)
    {
        const float* Kt = buf0 + t * TOKF;
        const float* Qt = buf1 + t * TOKF;
        unsigned long long kp[16];
#pragma unroll
        for (int j = 0; j < 16; j++)
            kp[j] = *(const unsigned long long*)(Kt + hp * SD + 2 * j);
#pragma unroll
        for (int hi = 0; hi < 8; hi++) {
            const int h = half * 8 + hi;
            const float* Qr = Qt + h * SD;
            unsigned long long a0 = 0, a1 = 0;
#pragma unroll
            for (int j = 0; j < 8; j++) {
                fma2(a0, *(const unsigned long long*)(Qr + 4 * j),     kp[2 * j]);
                fma2(a1, *(const unsigned long long*)(Qr + 4 * j + 2), kp[2 * j + 1]);
            }
            Ss[t * SST + h * SSD + hp] = hsum2(a0) + hsum2(a1);
        }
        if (half == 0) {
            const float* Qh = Qt + hp * SD;
            const float* Km = Ksm + hp * SD;
            unsigned long long a0 = 0, a1 = 0;
#pragma unroll
            for (int j = 0; j < 8; j++) {
                fma2(a0, *(const unsigned long long*)(Qh + 4 * j),
                         *(const unsigned long long*)(Km + 4 * j));
                fma2(a1, *(const unsigned long long*)(Qh + 4 * j + 2),
                         *(const unsigned long long*)(Km + 4 * j + 2));
            }
            Zs[t * 18 + hp] = 1.f / (hsum2(a0) + hsum2(a1) + 1e-5f);
        }
    }
    __syncthreads();

    // wide load V -> buf1 (overwrites Q)
    for (int c = tid; c < CH; c += 256) {
        const int off = (c >> 5) * SD + (c & 31);
        uint4 vu = *(const uint4*)&g_V[base + (size_t)c * NTOK];
        const __nv_bfloat162* vh = (const __nv_bfloat162*)&vu;
#pragma unroll
        for (int j = 0; j < 4; j++) {
            float2 vf = __bfloat1622float2(vh[j]);
            buf1[(2 * j)     * TOKF + off] = vf.x;
            buf1[(2 * j + 1) * TOKF + off] = vf.y;
        }
    }
    __syncthreads();

    // Phase B: O = diag(Z) S V -> buf0
    {
        const float* Vt = buf1 + t * TOKF;
        float vc[16];
#pragma unroll
        for (int q = 0; q < 16; q++) vc[q] = Vt[q * SD + lane];
        unsigned long long vp[8];
#pragma unroll
        for (int j = 0; j < 8; j++) vp[j] = pk2(vc[2 * j], vc[2 * j + 1]);
#pragma unroll
        for (int h = 0; h < 16; h++) {
            const unsigned long long* Sr =
                (const unsigned long long*)(Ss + t * SST + h * SSD);
            unsigned long long a0 = 0, a1 = 0;
#pragma unroll
            for (int j = 0; j < 4; j++) {
                fma2(a0, Sr[2 * j],     vp[2 * j]);
                fma2(a1, Sr[2 * j + 1], vp[2 * j + 1]);
            }
            buf0[t * TOKF + h * SD + lane] = (hsum2(a0) + hsum2(a1)) * Zs[t * 18 + h];
        }
    }
    __syncthreads();

    // wide store: pack 8 tokens per c-row into one uint4
    for (int c = tid; c < CH; c += 256) {
        const int off = (c >> 5) * SD + (c & 31);
        uint4 o;
        uint32_t* o32 = (uint32_t*)&o;
#pragma unroll
        for (int j = 0; j < 4; j++) {
            float2 f = make_float2(buf0[(2 * j) * TOKF + off],
                                   buf0[(2 * j + 1) * TOKF + off]);
            o32[j] = bf2u(__float22bfloat162_rn(f));
        }
        *(uint4*)&g_M[base + (size_t)c * NTOK] = o;
    }
}

// =====================================================================
extern "C" void kernel_launch(void* const* d_in, const int* in_sizes, int n_in,
                              void* d_out, int out_size)
{
    (void)in_sizes; (void)n_in; (void)out_size;
    const float* q  = (const float*)d_in[0];
    const float* k  = (const float*)d_in[1];
    const float* v  = (const float*)d_in[2];
    const float* Wq = (const float*)d_in[3];
    const float* Wk = (const float*)d_in[4];
    const float* Wv = (const float*)d_in[5];
    const float* Wp = (const float*)d_in[6];
    const float* bp = (const float*)d_in[7];
    float* out = (float*)d_out;

    void *wt, *x, *Qp, *Kp, *Vp, *Mp;
    cudaGetSymbolAddress(&wt, g_Wt);
    cudaGetSymbolAddress(&x,  g_X);
    cudaGetSymbolAddress(&Qp, g_Q);
    cudaGetSymbolAddress(&Kp, g_K);
    cudaGetSymbolAddress(&Vp, g_V);
    cudaGetSymbolAddress(&Mp, g_M);
    __nv_bfloat16* Wt = (__nv_bfloat16*)wt;
    __nv_bfloat16* X  = (__nv_bfloat16*)x;
    const size_t XS = (size_t)BATCH * CH * NTOK;

    cudaFuncSetAttribute(gemm_ca<true,  __nv_bfloat16, false>,
                         cudaFuncAttributeMaxDynamicSharedMemorySize, GEMM_SMEM);
    cudaFuncSetAttribute(gemm_ca<false, float, true>,
                         cudaFuncAttributeMaxDynamicSharedMemorySize, GEMM_SMEM);
    cudaFuncSetAttribute(mid_kernel,
                         cudaFuncAttributeMaxDynamicSharedMemorySize, MID_SMEM);

    // 1. prep (wprep also zeroes g_Ksum)
    wprep<<<dim3(16, 16, 4), 256>>>(Wq, Wk, Wv, Wp, Wt);
    xconv<<<dim3(8192, 1, 3), 256>>>((const float4*)q, (const float4*)k,
                                     (const float4*)v, (uint4*)X);

    // 2. projections (fused 3-in-1; K-proj accumulates Ksum via atomics)
    dim3 gp(NTOK / 128, CH / 128, 3 * BATCH);
    gemm_ca<true, __nv_bfloat16, false><<<gp, 256, GEMM_SMEM>>>(
        Wt, Wt + CH * CH, Wt + 2 * CH * CH,
        X, X + XS, X + 2 * XS,
        Qp, Kp, Vp, nullptr);

    // 3. middle
    mid_kernel<<<BATCH * (NTOK / TN), 256, MID_SMEM>>>();

    // 4. output projection
    dim3 gf(NTOK / 128, CH / 128, BATCH);
    gemm_ca<false, float, true><<<gf, 256, GEMM_SMEM>>>(
        Wt + 3 * CH * CH, nullptr, nullptr,
        (__nv_bfloat16*)Mp, nullptr, nullptr,
        out, nullptr, nullptr, bp);
}